// round 11
// baseline (speedup 1.0000x reference)
#include <cuda_runtime.h>
#include <math.h>
#include <stdint.h>

#define NODE 112
#define L1D 256
#define L2D 128
#define L3D 64
#define BATCH 2048
#define K1P 56
#define K2P 28

// ---------------- global scratch ----------------
__device__ float g_H0[NODE * L1D];            // projected identity features [n][o]
__device__ float g_E1[NODE * NODE];
__device__ float g_Wp2T[L1D * L2D];           // Wp2 transposed [d][o]
__device__ float g_h1[(size_t)BATCH * NODE * L1D];
__device__ float g_hp[(size_t)BATCH * K1P * L1D];
__device__ float g_adj[(size_t)BATCH * K1P * K1P];
__device__ float g_dummy;

// ---------------- K-preA ----------------
__global__ void k_preA(const float* __restrict__ Wp1, const float* __restrict__ bp1,
                       const float* __restrict__ Wp2) {
    int t = blockIdx.x * blockDim.x + threadIdx.x;
    int NT = gridDim.x * blockDim.x;
    for (int idx = t; idx < NODE * L1D; idx += NT) {
        int o = idx / NODE, n = idx - o * NODE;
        g_H0[n * L1D + o] = Wp1[idx] + bp1[o];
    }
    for (int idx = t; idx < L1D * L2D; idx += NT) {
        int o = idx >> 8, d = idx & 255;
        g_Wp2T[d * L2D + o] = Wp2[idx];
    }
}

// ---------------- K-preB ----------------
__global__ void k_preB(const float* __restrict__ wa1, const float* __restrict__ wb1,
                       const float* __restrict__ ba1) {
    __shared__ float s1[NODE], t1[NODE];
    int t = threadIdx.x;
    if (t < NODE) {
        float ss = 0.f, tt = 0.f;
        #pragma unroll 4
        for (int o = 0; o < L1D; o++) {
            float h = g_H0[t * L1D + o];
            ss = fmaf(h, wa1[o], ss);
            tt = fmaf(h, wb1[o], tt);
        }
        s1[t] = ss; t1[t] = tt;
    }
    __syncthreads();
    float ba = ba1[0];
    for (int idx = t; idx < NODE * NODE; idx += blockDim.x) {
        int i = idx / NODE, j = idx - i * NODE;
        float e = s1[i] + t1[j] + ba;
        e = e > 0.f ? e : 0.f;
        g_E1[idx] = expf(e);
    }
}

__global__ void k_tail() { if (threadIdx.x == 0) g_dummy = 1.f; }

// ---------------- K2: GAT1 + pool1 (occ 3, row-halves, scalar FFMA) -------
// smem: Ws[56*116] | H0t[112*64] | invr[64] | scr[128] | skey[128] | sidx[128]
// adjb[56*57] overlays H0t after GEMMs.
#define V_WS_STR 116
#define V_WS    0
#define V_H0T   (56 * V_WS_STR)                // 6496
#define V_INVR  (V_H0T + NODE * 64)            // 13664
#define V_SCR   (V_INVR + 64)
#define V_SKEY  (V_SCR + 128)
#define V_SIDX  (V_SKEY + 128)
#define V_TOT   (V_SIDX + 128)                 // 14112 floats = 56448 B

__global__ void __launch_bounds__(256, 3)
k_gat1(const float* __restrict__ x, const float* __restrict__ Wpool1,
       const float* __restrict__ bpool1) {
    extern __shared__ float sm[];
    float* Ws   = sm + V_WS;
    float* H0t  = sm + V_H0T;
    float* invr = sm + V_INVR;
    float* scr  = sm + V_SCR;
    float* skey = sm + V_SKEY;
    int*   sidx = (int*)(sm + V_SIDX);
    float* adjb = sm + V_H0T;                  // overlay (3192 <= 7168)

    int b = blockIdx.x;
    int t = threadIdx.x;
    const float* xb = x + (size_t)b * NODE * NODE;
    int l = t & 31, w = t >> 5;
    int rg = l >> 2, cg = l & 3;
    int row0 = rg * 7;                         // rows within half (0..55)
    int cb = w * 8 + cg * 2;                   // cols within 64-col tile
    float* h1b = g_h1 + (size_t)b * NODE * L1D;

    if (t < NODE) scr[t] = 0.f;

    for (int half = 0; half < 2; half++) {
        int rbase = half * 56;
        __syncthreads();   // prior-phase readers of Ws done; scr init visible
        // fill Ws = E1 .* x for this row half
        for (int idx = t; idx < 56 * NODE; idx += 256) {
            int i2 = idx / NODE, j = idx - i2 * NODE;
            int gi = (rbase + i2) * NODE + j;
            Ws[i2 * V_WS_STR + j] = g_E1[gi] * xb[gi];
        }
        __syncthreads();
        // warp-parallel row sums: warp w owns rows w*7..w*7+6
        {
            int i2 = w * 7;
            #pragma unroll
            for (int rr = 0; rr < 7; rr++, i2++) {
                const float* wr = &Ws[i2 * V_WS_STR];
                float s = wr[l] + wr[32 + l] + wr[64 + l];
                if (l < 16) s += wr[96 + l];
                s += __shfl_xor_sync(0xffffffffu, s, 16);
                s += __shfl_xor_sync(0xffffffffu, s, 8);
                s += __shfl_xor_sync(0xffffffffu, s, 4);
                s += __shfl_xor_sync(0xffffffffu, s, 2);
                s += __shfl_xor_sync(0xffffffffu, s, 1);
                if (l == 0) invr[i2] = 1.f / s;
            }
        }
        for (int ct = 0; ct < 4; ct++) {
            __syncthreads();   // H0t overwrite safe; invr visible on first ct
            for (int idx = t; idx < NODE * 64; idx += 256) {
                int j = idx >> 6, c = idx & 63;
                H0t[idx] = g_H0[j * L1D + ct * 64 + c];
            }
            __syncthreads();
            float wc0 = Wpool1[ct * 64 + cb];
            float wc1 = Wpool1[ct * 64 + cb + 1];
            float acc[7][2];
            #pragma unroll
            for (int r = 0; r < 7; r++) { acc[r][0] = 0.f; acc[r][1] = 0.f; }

            #pragma unroll 2
            for (int j4 = 0; j4 < 28; j4++) {
                float2 b0 = *(const float2*)&H0t[(j4 * 4 + 0) * 64 + cb];
                float2 b1 = *(const float2*)&H0t[(j4 * 4 + 1) * 64 + cb];
                float2 b2 = *(const float2*)&H0t[(j4 * 4 + 2) * 64 + cb];
                float2 b3 = *(const float2*)&H0t[(j4 * 4 + 3) * 64 + cb];
                #pragma unroll
                for (int r = 0; r < 7; r++) {
                    float4 a = *(const float4*)&Ws[(row0 + r) * V_WS_STR + j4 * 4];
                    acc[r][0] = fmaf(a.x, b0.x, acc[r][0]);
                    acc[r][1] = fmaf(a.x, b0.y, acc[r][1]);
                    acc[r][0] = fmaf(a.y, b1.x, acc[r][0]);
                    acc[r][1] = fmaf(a.y, b1.y, acc[r][1]);
                    acc[r][0] = fmaf(a.z, b2.x, acc[r][0]);
                    acc[r][1] = fmaf(a.z, b2.y, acc[r][1]);
                    acc[r][0] = fmaf(a.w, b3.x, acc[r][0]);
                    acc[r][1] = fmaf(a.w, b3.y, acc[r][1]);
                }
            }
            #pragma unroll
            for (int r = 0; r < 7; r++) {
                int i2 = row0 + r;
                int ig = rbase + i2;
                float ir = invr[i2];
                float2 h0 = *(const float2*)&H0t[ig * 64 + cb];
                float v0 = fmaxf(fmaf(acc[r][0], ir, h0.x), 0.f);
                float v1 = fmaxf(fmaf(acc[r][1], ir, h0.y), 0.f);
                *(float2*)&h1b[ig * L1D + ct * 64 + cb] = make_float2(v0, v1);
                float sp = v0 * wc0 + v1 * wc1;
                sp += __shfl_xor_sync(0xffffffffu, sp, 1);
                sp += __shfl_xor_sync(0xffffffffu, sp, 2);
                if (cg == 0) atomicAdd(&scr[ig], sp);
            }
        }
    }
    __syncthreads();

    // sigmoid + bitonic top-56 (pad 128)
    if (t < 128) {
        if (t < NODE) {
            skey[t] = 1.f / (1.f + expf(-(scr[t] + bpool1[0])));
            sidx[t] = t;
        } else { skey[t] = -1.f; sidx[t] = t; }
    }
    __syncthreads();
    for (int k = 2; k <= 128; k <<= 1) {
        for (int j = k >> 1; j > 0; j >>= 1) {
            if (t < 128) {
                int lp = t ^ j;
                if (lp > t) {
                    float a = skey[t], c = skey[lp];
                    int ia = sidx[t], ib = sidx[lp];
                    bool before = (a > c) || (a == c && ia < ib);
                    if (((t & k) == 0) ? !before : before) {
                        skey[t] = c; skey[lp] = a;
                        sidx[t] = ib; sidx[lp] = ia;
                    }
                }
            }
            __syncthreads();
        }
    }

    float* hpb = g_hp + (size_t)b * K1P * L1D;
    for (int idx = t; idx < K1P * L1D; idx += 256) {
        int m = idx >> 8, c = idx & 255;
        hpb[idx] = h1b[sidx[m] * L1D + c] * skey[m];
    }
    for (int idx = t; idx < K1P * K1P; idx += 256) {
        int i = idx / K1P, j = idx - i * K1P;
        adjb[i * 57 + j] = xb[sidx[i] * NODE + sidx[j]];
    }
    __syncthreads();
    if (t < K1P) {
        float s = 0.f;
        for (int j = 0; j < K1P; j++) s += adjb[t * 57 + j];
        invr[t] = 1.f / s;
    }
    __syncthreads();
    float* adjo = g_adj + (size_t)b * K1P * K1P;
    for (int idx = t; idx < K1P * K1P; idx += 256) {
        int i = idx / K1P, j = idx - i * K1P;
        adjo[idx] = adjb[i * 57 + j] * invr[i];
    }
}

// ---------------- K3: GAT2 + pool2 + mean + FC head (occ 3) ----------------
#define HST_STR  36
#define ATT_STR  60
#define H2P_STR  132
#define G2_OVL   0
#define G2_W2P   (56 * HST_STR)               // 2016
#define G2_H2P   6112
#define G2_S2    (G2_H2P + K1P * H2P_STR)     // 13504
#define G2_T2    (G2_S2 + 64)
#define G2_SC2   (G2_T2 + 64)
#define G2_INVR  (G2_SC2 + 64)
#define G2_SKEY  (G2_INVR + 64)
#define G2_SIDX  (G2_SKEY + 64)
#define G2_MVEC  (G2_SIDX + 64)
#define G2_Y1    (G2_MVEC + 128)
#define G2_FLOATS (G2_Y1 + 64)

__global__ void __launch_bounds__(256, 3)
k_gat2(const float* __restrict__ bp2, const float* __restrict__ wa2,
       const float* __restrict__ wb2, const float* __restrict__ ba2,
       const float* __restrict__ Wpool2, const float* __restrict__ bpool2,
       const float* __restrict__ Wfc1, const float* __restrict__ bfc1,
       const float* __restrict__ Wfc2, const float* __restrict__ bfc2,
       float* __restrict__ out) {
    extern __shared__ float sm[];
    float* Hst  = sm + G2_OVL;                // [56][36]
    float* W2p  = sm + G2_W2P;                // [32][128]
    float* atts = sm + G2_OVL;                // overlays Hst/W2p after GEMM1
    float* h2p  = sm + G2_H2P;                // [56][132]
    float* s2   = sm + G2_S2;
    float* t2   = sm + G2_T2;
    float* sc2  = sm + G2_SC2;
    float* invr = sm + G2_INVR;
    float* skey = sm + G2_SKEY;
    int*   sidx = (int*)(sm + G2_SIDX);
    float* mvec = sm + G2_MVEC;
    float* y1   = sm + G2_Y1;

    int b = blockIdx.x;
    int t = threadIdx.x;
    const float* hpb = g_hp + (size_t)b * K1P * L1D;

    if (t < K1P) { s2[t] = 0.f; t2[t] = 0.f; sc2[t] = 0.f; }

    int l = t & 31, w = t >> 5;
    int rg = l >> 2, cg = l & 3;
    int row0 = rg * 7;
    int cb = w * 16 + cg * 4;

    // GEMM1: h2 = Hs @ Wp2^T + bp2 (56x256 @ 256x128), K tiled by 32
    float acc[7][4];
    #pragma unroll
    for (int r = 0; r < 7; r++) { acc[r][0]=0.f; acc[r][1]=0.f; acc[r][2]=0.f; acc[r][3]=0.f; }
    for (int dt = 0; dt < 8; dt++) {
        for (int idx = t; idx < 56 * 32; idx += 256) {
            int i = idx >> 5, dd = idx & 31;
            Hst[i * HST_STR + dd] = hpb[i * L1D + dt * 32 + dd];
        }
        for (int idx = t; idx < 32 * 128; idx += 256)
            W2p[idx] = g_Wp2T[dt * 4096 + idx];
        __syncthreads();
        #pragma unroll
        for (int d4 = 0; d4 < 8; d4++) {
            float4 b0 = *(const float4*)&W2p[(d4 * 4 + 0) * 128 + cb];
            float4 b1 = *(const float4*)&W2p[(d4 * 4 + 1) * 128 + cb];
            float4 b2 = *(const float4*)&W2p[(d4 * 4 + 2) * 128 + cb];
            float4 b3 = *(const float4*)&W2p[(d4 * 4 + 3) * 128 + cb];
            #pragma unroll
            for (int r = 0; r < 7; r++) {
                float4 a = *(const float4*)&Hst[(row0 + r) * HST_STR + d4 * 4];
                acc[r][0] = fmaf(a.x, b0.x, acc[r][0]);
                acc[r][1] = fmaf(a.x, b0.y, acc[r][1]);
                acc[r][2] = fmaf(a.x, b0.z, acc[r][2]);
                acc[r][3] = fmaf(a.x, b0.w, acc[r][3]);
                acc[r][0] = fmaf(a.y, b1.x, acc[r][0]);
                acc[r][1] = fmaf(a.y, b1.y, acc[r][1]);
                acc[r][2] = fmaf(a.y, b1.z, acc[r][2]);
                acc[r][3] = fmaf(a.y, b1.w, acc[r][3]);
                acc[r][0] = fmaf(a.z, b2.x, acc[r][0]);
                acc[r][1] = fmaf(a.z, b2.y, acc[r][1]);
                acc[r][2] = fmaf(a.z, b2.z, acc[r][2]);
                acc[r][3] = fmaf(a.z, b2.w, acc[r][3]);
                acc[r][0] = fmaf(a.w, b3.x, acc[r][0]);
                acc[r][1] = fmaf(a.w, b3.y, acc[r][1]);
                acc[r][2] = fmaf(a.w, b3.z, acc[r][2]);
                acc[r][3] = fmaf(a.w, b3.w, acc[r][3]);
            }
        }
        __syncthreads();
    }
    {
        const float* bpp = bp2 + cb;
        float b0 = bpp[0], b1 = bpp[1], b2 = bpp[2], b3 = bpp[3];
        const float* wap = wa2 + cb;
        const float* wbp = wb2 + cb;
        float wa0=wap[0], wa1v=wap[1], wa2v=wap[2], wa3=wap[3];
        float wb0=wbp[0], wb1v=wbp[1], wb2v=wbp[2], wb3=wbp[3];
        #pragma unroll
        for (int r = 0; r < 7; r++) {
            int i = row0 + r;
            float v0 = acc[r][0] + b0, v1 = acc[r][1] + b1;
            float v2 = acc[r][2] + b2, v3 = acc[r][3] + b3;
            *(float4*)&h2p[i * H2P_STR + cb] = make_float4(v0, v1, v2, v3);
            float ssum = v0*wa0 + v1*wa1v + v2*wa2v + v3*wa3;
            float tsum = v0*wb0 + v1*wb1v + v2*wb2v + v3*wb3;
            ssum += __shfl_xor_sync(0xffffffffu, ssum, 1);
            ssum += __shfl_xor_sync(0xffffffffu, ssum, 2);
            tsum += __shfl_xor_sync(0xffffffffu, tsum, 1);
            tsum += __shfl_xor_sync(0xffffffffu, tsum, 2);
            if (cg == 0) {
                atomicAdd(&s2[i], ssum);
                atomicAdd(&t2[i], tsum);
            }
        }
    }
    __syncthreads();

    // attention weights (atts overlays Hst/W2p)
    float ba = ba2[0];
    const float* adjg = g_adj + (size_t)b * K1P * K1P;
    for (int idx = t; idx < K1P * K1P; idx += 256) {
        int i = idx / K1P, j = idx - i * K1P;
        float e = s2[i] + t2[j] + ba;
        e = e > 0.f ? e : 0.f;
        atts[i * ATT_STR + j] = expf(e) * adjg[idx];
    }
    __syncthreads();
    if (t < K1P) {
        float s = 0.f;
        for (int j = 0; j < K1P; j++) s += atts[t * ATT_STR + j];
        invr[t] = 1.f / s;
    }
    __syncthreads();

    // GEMM2: out2 = att_norm @ h2 + h2, relu (in-place into h2p)
    float acc2[7][4];
    #pragma unroll
    for (int r = 0; r < 7; r++) { acc2[r][0]=0.f; acc2[r][1]=0.f; acc2[r][2]=0.f; acc2[r][3]=0.f; }
    #pragma unroll 2
    for (int j4 = 0; j4 < 14; j4++) {
        float4 b0 = *(const float4*)&h2p[(j4 * 4 + 0) * H2P_STR + cb];
        float4 b1 = *(const float4*)&h2p[(j4 * 4 + 1) * H2P_STR + cb];
        float4 b2 = *(const float4*)&h2p[(j4 * 4 + 2) * H2P_STR + cb];
        float4 b3 = *(const float4*)&h2p[(j4 * 4 + 3) * H2P_STR + cb];
        #pragma unroll
        for (int r = 0; r < 7; r++) {
            float4 a = *(const float4*)&atts[(row0 + r) * ATT_STR + j4 * 4];
            acc2[r][0] = fmaf(a.x, b0.x, acc2[r][0]);
            acc2[r][1] = fmaf(a.x, b0.y, acc2[r][1]);
            acc2[r][2] = fmaf(a.x, b0.z, acc2[r][2]);
            acc2[r][3] = fmaf(a.x, b0.w, acc2[r][3]);
            acc2[r][0] = fmaf(a.y, b1.x, acc2[r][0]);
            acc2[r][1] = fmaf(a.y, b1.y, acc2[r][1]);
            acc2[r][2] = fmaf(a.y, b1.z, acc2[r][2]);
            acc2[r][3] = fmaf(a.y, b1.w, acc2[r][3]);
            acc2[r][0] = fmaf(a.z, b2.x, acc2[r][0]);
            acc2[r][1] = fmaf(a.z, b2.y, acc2[r][1]);
            acc2[r][2] = fmaf(a.z, b2.z, acc2[r][2]);
            acc2[r][3] = fmaf(a.z, b2.w, acc2[r][3]);
            acc2[r][0] = fmaf(a.w, b3.x, acc2[r][0]);
            acc2[r][1] = fmaf(a.w, b3.y, acc2[r][1]);
            acc2[r][2] = fmaf(a.w, b3.z, acc2[r][2]);
            acc2[r][3] = fmaf(a.w, b3.w, acc2[r][3]);
        }
    }
    __syncthreads();
    {
        const float* wpp = Wpool2 + cb;
        float w0 = wpp[0], w1 = wpp[1], w2 = wpp[2], w3 = wpp[3];
        #pragma unroll
        for (int r = 0; r < 7; r++) {
            int i = row0 + r;
            float ir = invr[i];
            float4 hself = *(const float4*)&h2p[i * H2P_STR + cb];
            float4 v;
            v.x = fmaxf(fmaf(acc2[r][0], ir, hself.x), 0.f);
            v.y = fmaxf(fmaf(acc2[r][1], ir, hself.y), 0.f);
            v.z = fmaxf(fmaf(acc2[r][2], ir, hself.z), 0.f);
            v.w = fmaxf(fmaf(acc2[r][3], ir, hself.w), 0.f);
            *(float4*)&h2p[i * H2P_STR + cb] = v;
            float sp = v.x*w0 + v.y*w1 + v.z*w2 + v.w*w3;
            sp += __shfl_xor_sync(0xffffffffu, sp, 1);
            sp += __shfl_xor_sync(0xffffffffu, sp, 2);
            if (cg == 0) atomicAdd(&sc2[i], sp);
        }
    }
    __syncthreads();

    // top-28 of 56 (pad 64)
    if (t < 64) {
        if (t < K1P) {
            skey[t] = 1.f / (1.f + expf(-(sc2[t] + bpool2[0])));
            sidx[t] = t;
        } else { skey[t] = -1.f; sidx[t] = t; }
    }
    __syncthreads();
    for (int k = 2; k <= 64; k <<= 1) {
        for (int j = k >> 1; j > 0; j >>= 1) {
            if (t < 64) {
                int lp = t ^ j;
                if (lp > t) {
                    float a = skey[t], c = skey[lp];
                    int ia = sidx[t], ib = sidx[lp];
                    bool before = (a > c) || (a == c && ia < ib);
                    if (((t & k) == 0) ? !before : before) {
                        skey[t] = c; skey[lp] = a;
                        sidx[t] = ib; sidx[lp] = ia;
                    }
                }
            }
            __syncthreads();
        }
    }

    if (t < L2D) {
        float s = 0.f;
        #pragma unroll 4
        for (int m = 0; m < K2P; m++)
            s += h2p[sidx[m] * H2P_STR + t] * skey[m];
        mvec[t] = s * (1.f / (float)K2P);
    }
    __syncthreads();
    if (t < L3D) {
        float s = bfc1[t];
        #pragma unroll 8
        for (int d = 0; d < L2D; d++) s = fmaf(mvec[d], Wfc1[t * L2D + d], s);
        y1[t] = fmaxf(s, 0.f);
    }
    __syncthreads();
    if (t == 0) {
        float s = bfc2[0];
        for (int o = 0; o < L3D; o++) s = fmaf(y1[o], Wfc2[o], s);
        out[b] = s;
    }
}

// ---------------- launch ----------------
extern "C" void kernel_launch(void* const* d_in, const int* in_sizes, int n_in,
                              void* d_out, int out_size) {
    const float* x      = (const float*)d_in[0];
    const float* Wp1    = (const float*)d_in[1];
    const float* bp1    = (const float*)d_in[2];
    const float* wa1    = (const float*)d_in[3];
    const float* wb1    = (const float*)d_in[4];
    const float* ba1    = (const float*)d_in[5];
    const float* Wpool1 = (const float*)d_in[6];
    const float* bpool1 = (const float*)d_in[7];
    const float* Wp2    = (const float*)d_in[8];
    const float* bp2    = (const float*)d_in[9];
    const float* wa2    = (const float*)d_in[10];
    const float* wb2    = (const float*)d_in[11];
    const float* ba2    = (const float*)d_in[12];
    const float* Wpool2 = (const float*)d_in[13];
    const float* bpool2 = (const float*)d_in[14];
    const float* Wfc1   = (const float*)d_in[15];
    const float* bfc1   = (const float*)d_in[16];
    const float* Wfc2   = (const float*)d_in[17];
    const float* bfc2   = (const float*)d_in[18];
    float* out = (float*)d_out;

    size_t smem1 = (size_t)V_TOT * sizeof(float);
    size_t smem2 = (size_t)G2_FLOATS * sizeof(float);
    cudaFuncSetAttribute(k_gat1, cudaFuncAttributeMaxDynamicSharedMemorySize, (int)smem1);
    cudaFuncSetAttribute(k_gat2, cudaFuncAttributeMaxDynamicSharedMemorySize, (int)smem2);

    k_preA<<<32, 256>>>(Wp1, bp1, Wp2);
    k_preB<<<1, 256>>>(wa1, wb1, ba1);
    k_tail<<<1, 32>>>();
    k_gat1<<<BATCH, 256, smem1>>>(x, Wpool1, bpool1);
    k_gat2<<<BATCH, 256, smem2>>>(bp2, wa2, wb2, ba2, Wpool2, bpool2,
                                  Wfc1, bfc1, Wfc2, bfc2, out);
}

// round 14
// speedup vs baseline: 1.0483x; 1.0483x over previous
#include <cuda_runtime.h>
#include <math.h>
#include <stdint.h>

#define NODE 112
#define L1D 256
#define L2D 128
#define L3D 64
#define BATCH 2048
#define K1P 56
#define K2P 28

// ---------------- global scratch ----------------
__device__ float g_H0[NODE * L1D];            // projected identity features [n][o]
__device__ float g_E1[NODE * NODE];
__device__ float g_Wp2T[L1D * L2D];           // Wp2 transposed [d][o]
__device__ float g_h1[(size_t)BATCH * NODE * L1D];
__device__ float g_hp[(size_t)BATCH * K1P * L1D];
__device__ float g_adj[(size_t)BATCH * K1P * K1P];
__device__ float g_dummy;

// ---------------- K-preA ----------------
__global__ void k_preA(const float* __restrict__ Wp1, const float* __restrict__ bp1,
                       const float* __restrict__ Wp2) {
    int t = blockIdx.x * blockDim.x + threadIdx.x;
    int NT = gridDim.x * blockDim.x;
    for (int idx = t; idx < NODE * L1D; idx += NT) {
        int o = idx / NODE, n = idx - o * NODE;
        g_H0[n * L1D + o] = Wp1[idx] + bp1[o];
    }
    for (int idx = t; idx < L1D * L2D; idx += NT) {
        int o = idx >> 8, d = idx & 255;
        g_Wp2T[d * L2D + o] = Wp2[idx];
    }
}

// ---------------- K-preB ----------------
__global__ void k_preB(const float* __restrict__ wa1, const float* __restrict__ wb1,
                       const float* __restrict__ ba1) {
    __shared__ float s1[NODE], t1[NODE];
    int t = threadIdx.x;
    if (t < NODE) {
        float ss = 0.f, tt = 0.f;
        #pragma unroll 4
        for (int o = 0; o < L1D; o++) {
            float h = g_H0[t * L1D + o];
            ss = fmaf(h, wa1[o], ss);
            tt = fmaf(h, wb1[o], tt);
        }
        s1[t] = ss; t1[t] = tt;
    }
    __syncthreads();
    float ba = ba1[0];
    for (int idx = t; idx < NODE * NODE; idx += blockDim.x) {
        int i = idx / NODE, j = idx - i * NODE;
        float e = s1[i] + t1[j] + ba;
        e = e > 0.f ? e : 0.f;
        g_E1[idx] = expf(e);
    }
}

__global__ void k_tail() { if (threadIdx.x == 0) g_dummy = 1.f; }

// ---------------- K2: GAT1 + pool1 (occ 3, row-halves, k-split, 7x4 tile) --
// smem: Ws[56*116] | H0t[56*128] | invr[64] | scr[128] | skey[128] | sidx[128]
// adjb[56*57] overlays H0t after GEMMs.
#define V_WS_STR 116
#define V_WS    0
#define V_H0T   (56 * V_WS_STR)                // 6496
#define V_INVR  (V_H0T + 56 * 128)             // 13664
#define V_SCR   (V_INVR + 64)
#define V_SKEY  (V_SCR + 128)
#define V_SIDX  (V_SKEY + 128)
#define V_TOT   (V_SIDX + 128)                 // 14112 floats = 56448 B

__global__ void __launch_bounds__(256, 3)
k_gat1(const float* __restrict__ x, const float* __restrict__ Wpool1,
       const float* __restrict__ bpool1) {
    extern __shared__ float sm[];
    float* Ws   = sm + V_WS;
    float* H0t  = sm + V_H0T;                  // [56 k-rows][128 cols]
    float* invr = sm + V_INVR;
    float* scr  = sm + V_SCR;
    float* skey = sm + V_SKEY;
    int*   sidx = (int*)(sm + V_SIDX);
    float* adjb = sm + V_H0T;                  // overlay (3192 <= 7168)

    int b = blockIdx.x;
    int t = threadIdx.x;
    const float* xb = x + (size_t)b * NODE * NODE;
    int l = t & 31, w = t >> 5;
    int rg = l >> 2, cg = l & 3;
    int row0 = rg * 7;                         // rows within half (0..55)
    int cb = w * 16 + cg * 4;                  // cols within 128-col tile
    float* h1b = g_h1 + (size_t)b * NODE * L1D;

    if (t < NODE) scr[t] = 0.f;

    for (int half = 0; half < 2; half++) {
        int rbase = half * 56;
        __syncthreads();   // prior readers of Ws/invr done; scr init visible
        // fill Ws = E1 .* x for this row half
        for (int idx = t; idx < 56 * NODE; idx += 256) {
            int i2 = idx / NODE, j = idx - i2 * NODE;
            int gi = (rbase + i2) * NODE + j;
            Ws[i2 * V_WS_STR + j] = g_E1[gi] * xb[gi];
        }
        __syncthreads();
        // warp-parallel row sums: warp w owns rows w*7..w*7+6
        {
            int i2 = w * 7;
            #pragma unroll
            for (int rr = 0; rr < 7; rr++, i2++) {
                const float* wr = &Ws[i2 * V_WS_STR];
                float s = wr[l] + wr[32 + l] + wr[64 + l];
                if (l < 16) s += wr[96 + l];
                s += __shfl_xor_sync(0xffffffffu, s, 16);
                s += __shfl_xor_sync(0xffffffffu, s, 8);
                s += __shfl_xor_sync(0xffffffffu, s, 4);
                s += __shfl_xor_sync(0xffffffffu, s, 2);
                s += __shfl_xor_sync(0xffffffffu, s, 1);
                if (l == 0) invr[i2] = 1.f / s;
            }
        }
        for (int ct = 0; ct < 2; ct++) {       // 128-col tiles
            float acc[7][4];
            #pragma unroll
            for (int r = 0; r < 7; r++) { acc[r][0]=0.f; acc[r][1]=0.f; acc[r][2]=0.f; acc[r][3]=0.f; }
            #pragma unroll
            for (int s5 = 0; s5 < 2; s5++) {
                int kh = (s5 == 0) ? (half ^ 1) : half;   // own-rows tile last
                __syncthreads();               // previous H0t readers done
                for (int idx = t; idx < 56 * 128; idx += 256) {
                    int jr = idx >> 7, c = idx & 127;
                    H0t[idx] = g_H0[(kh * 56 + jr) * L1D + ct * 128 + c];
                }
                __syncthreads();
                int kb = kh * 56;
                #pragma unroll 2
                for (int j4 = 0; j4 < 14; j4++) {
                    float4 b0 = *(const float4*)&H0t[(j4 * 4 + 0) * 128 + cb];
                    float4 b1 = *(const float4*)&H0t[(j4 * 4 + 1) * 128 + cb];
                    float4 b2 = *(const float4*)&H0t[(j4 * 4 + 2) * 128 + cb];
                    float4 b3 = *(const float4*)&H0t[(j4 * 4 + 3) * 128 + cb];
                    #pragma unroll
                    for (int r = 0; r < 7; r++) {
                        float4 a = *(const float4*)&Ws[(row0 + r) * V_WS_STR + kb + j4 * 4];
                        acc[r][0] = fmaf(a.x, b0.x, acc[r][0]);
                        acc[r][1] = fmaf(a.x, b0.y, acc[r][1]);
                        acc[r][2] = fmaf(a.x, b0.z, acc[r][2]);
                        acc[r][3] = fmaf(a.x, b0.w, acc[r][3]);
                        acc[r][0] = fmaf(a.y, b1.x, acc[r][0]);
                        acc[r][1] = fmaf(a.y, b1.y, acc[r][1]);
                        acc[r][2] = fmaf(a.y, b1.z, acc[r][2]);
                        acc[r][3] = fmaf(a.y, b1.w, acc[r][3]);
                        acc[r][0] = fmaf(a.z, b2.x, acc[r][0]);
                        acc[r][1] = fmaf(a.z, b2.y, acc[r][1]);
                        acc[r][2] = fmaf(a.z, b2.z, acc[r][2]);
                        acc[r][3] = fmaf(a.z, b2.w, acc[r][3]);
                        acc[r][0] = fmaf(a.w, b3.x, acc[r][0]);
                        acc[r][1] = fmaf(a.w, b3.y, acc[r][1]);
                        acc[r][2] = fmaf(a.w, b3.z, acc[r][2]);
                        acc[r][3] = fmaf(a.w, b3.w, acc[r][3]);
                    }
                }
            }
            // epilogue: H0t currently holds k-rows [half*56, half*56+56)
            // == this half's own rows, local index i2.
            float wc0 = Wpool1[ct * 128 + cb];
            float wc1 = Wpool1[ct * 128 + cb + 1];
            float wc2 = Wpool1[ct * 128 + cb + 2];
            float wc3 = Wpool1[ct * 128 + cb + 3];
            #pragma unroll
            for (int r = 0; r < 7; r++) {
                int i2 = row0 + r;
                int ig = rbase + i2;
                float ir = invr[i2];
                float4 h0 = *(const float4*)&H0t[i2 * 128 + cb];
                float4 v;
                v.x = fmaxf(fmaf(acc[r][0], ir, h0.x), 0.f);
                v.y = fmaxf(fmaf(acc[r][1], ir, h0.y), 0.f);
                v.z = fmaxf(fmaf(acc[r][2], ir, h0.z), 0.f);
                v.w = fmaxf(fmaf(acc[r][3], ir, h0.w), 0.f);
                *(float4*)&h1b[ig * L1D + ct * 128 + cb] = v;
                float sp = v.x*wc0 + v.y*wc1 + v.z*wc2 + v.w*wc3;
                sp += __shfl_xor_sync(0xffffffffu, sp, 1);
                sp += __shfl_xor_sync(0xffffffffu, sp, 2);
                if (cg == 0) atomicAdd(&scr[ig], sp);
            }
        }
    }
    __syncthreads();

    // sigmoid + bitonic top-56 (pad 128)
    if (t < 128) {
        if (t < NODE) {
            skey[t] = 1.f / (1.f + expf(-(scr[t] + bpool1[0])));
            sidx[t] = t;
        } else { skey[t] = -1.f; sidx[t] = t; }
    }
    __syncthreads();
    for (int k = 2; k <= 128; k <<= 1) {
        for (int j = k >> 1; j > 0; j >>= 1) {
            if (t < 128) {
                int lp = t ^ j;
                if (lp > t) {
                    float a = skey[t], c = skey[lp];
                    int ia = sidx[t], ib = sidx[lp];
                    bool before = (a > c) || (a == c && ia < ib);
                    if (((t & k) == 0) ? !before : before) {
                        skey[t] = c; skey[lp] = a;
                        sidx[t] = ib; sidx[lp] = ia;
                    }
                }
            }
            __syncthreads();
        }
    }

    float* hpb = g_hp + (size_t)b * K1P * L1D;
    for (int idx = t; idx < K1P * L1D; idx += 256) {
        int m = idx >> 8, c = idx & 255;
        hpb[idx] = h1b[sidx[m] * L1D + c] * skey[m];
    }
    for (int idx = t; idx < K1P * K1P; idx += 256) {
        int i = idx / K1P, j = idx - i * K1P;
        adjb[i * 57 + j] = xb[sidx[i] * NODE + sidx[j]];
    }
    __syncthreads();
    if (t < K1P) {
        float s = 0.f;
        for (int j = 0; j < K1P; j++) s += adjb[t * 57 + j];
        invr[t] = 1.f / s;
    }
    __syncthreads();
    float* adjo = g_adj + (size_t)b * K1P * K1P;
    for (int idx = t; idx < K1P * K1P; idx += 256) {
        int i = idx / K1P, j = idx - i * K1P;
        adjo[idx] = adjb[i * 57 + j] * invr[i];
    }
}

// ---------------- K3: GAT2 + pool2 + mean + FC head (occ 3, unchanged) ----
#define HST_STR  36
#define ATT_STR  60
#define H2P_STR  132
#define G2_OVL   0
#define G2_W2P   (56 * HST_STR)               // 2016
#define G2_H2P   6112
#define G2_S2    (G2_H2P + K1P * H2P_STR)     // 13504
#define G2_T2    (G2_S2 + 64)
#define G2_SC2   (G2_T2 + 64)
#define G2_INVR  (G2_SC2 + 64)
#define G2_SKEY  (G2_INVR + 64)
#define G2_SIDX  (G2_SKEY + 64)
#define G2_MVEC  (G2_SIDX + 64)
#define G2_Y1    (G2_MVEC + 128)
#define G2_FLOATS (G2_Y1 + 64)

__global__ void __launch_bounds__(256, 3)
k_gat2(const float* __restrict__ bp2, const float* __restrict__ wa2,
       const float* __restrict__ wb2, const float* __restrict__ ba2,
       const float* __restrict__ Wpool2, const float* __restrict__ bpool2,
       const float* __restrict__ Wfc1, const float* __restrict__ bfc1,
       const float* __restrict__ Wfc2, const float* __restrict__ bfc2,
       float* __restrict__ out) {
    extern __shared__ float sm[];
    float* Hst  = sm + G2_OVL;
    float* W2p  = sm + G2_W2P;
    float* atts = sm + G2_OVL;
    float* h2p  = sm + G2_H2P;
    float* s2   = sm + G2_S2;
    float* t2   = sm + G2_T2;
    float* sc2  = sm + G2_SC2;
    float* invr = sm + G2_INVR;
    float* skey = sm + G2_SKEY;
    int*   sidx = (int*)(sm + G2_SIDX);
    float* mvec = sm + G2_MVEC;
    float* y1   = sm + G2_Y1;

    int b = blockIdx.x;
    int t = threadIdx.x;
    const float* hpb = g_hp + (size_t)b * K1P * L1D;

    if (t < K1P) { s2[t] = 0.f; t2[t] = 0.f; sc2[t] = 0.f; }

    int l = t & 31, w = t >> 5;
    int rg = l >> 2, cg = l & 3;
    int row0 = rg * 7;
    int cb = w * 16 + cg * 4;

    float acc[7][4];
    #pragma unroll
    for (int r = 0; r < 7; r++) { acc[r][0]=0.f; acc[r][1]=0.f; acc[r][2]=0.f; acc[r][3]=0.f; }
    for (int dt = 0; dt < 8; dt++) {
        for (int idx = t; idx < 56 * 32; idx += 256) {
            int i = idx >> 5, dd = idx & 31;
            Hst[i * HST_STR + dd] = hpb[i * L1D + dt * 32 + dd];
        }
        for (int idx = t; idx < 32 * 128; idx += 256)
            W2p[idx] = g_Wp2T[dt * 4096 + idx];
        __syncthreads();
        #pragma unroll
        for (int d4 = 0; d4 < 8; d4++) {
            float4 b0 = *(const float4*)&W2p[(d4 * 4 + 0) * 128 + cb];
            float4 b1 = *(const float4*)&W2p[(d4 * 4 + 1) * 128 + cb];
            float4 b2 = *(const float4*)&W2p[(d4 * 4 + 2) * 128 + cb];
            float4 b3 = *(const float4*)&W2p[(d4 * 4 + 3) * 128 + cb];
            #pragma unroll
            for (int r = 0; r < 7; r++) {
                float4 a = *(const float4*)&Hst[(row0 + r) * HST_STR + d4 * 4];
                acc[r][0] = fmaf(a.x, b0.x, acc[r][0]);
                acc[r][1] = fmaf(a.x, b0.y, acc[r][1]);
                acc[r][2] = fmaf(a.x, b0.z, acc[r][2]);
                acc[r][3] = fmaf(a.x, b0.w, acc[r][3]);
                acc[r][0] = fmaf(a.y, b1.x, acc[r][0]);
                acc[r][1] = fmaf(a.y, b1.y, acc[r][1]);
                acc[r][2] = fmaf(a.y, b1.z, acc[r][2]);
                acc[r][3] = fmaf(a.y, b1.w, acc[r][3]);
                acc[r][0] = fmaf(a.z, b2.x, acc[r][0]);
                acc[r][1] = fmaf(a.z, b2.y, acc[r][1]);
                acc[r][2] = fmaf(a.z, b2.z, acc[r][2]);
                acc[r][3] = fmaf(a.z, b2.w, acc[r][3]);
                acc[r][0] = fmaf(a.w, b3.x, acc[r][0]);
                acc[r][1] = fmaf(a.w, b3.y, acc[r][1]);
                acc[r][2] = fmaf(a.w, b3.z, acc[r][2]);
                acc[r][3] = fmaf(a.w, b3.w, acc[r][3]);
            }
        }
        __syncthreads();
    }
    {
        const float* bpp = bp2 + cb;
        float b0 = bpp[0], b1 = bpp[1], b2 = bpp[2], b3 = bpp[3];
        const float* wap = wa2 + cb;
        const float* wbp = wb2 + cb;
        float wa0=wap[0], wa1v=wap[1], wa2v=wap[2], wa3=wap[3];
        float wb0=wbp[0], wb1v=wbp[1], wb2v=wbp[2], wb3=wbp[3];
        #pragma unroll
        for (int r = 0; r < 7; r++) {
            int i = row0 + r;
            float v0 = acc[r][0] + b0, v1 = acc[r][1] + b1;
            float v2 = acc[r][2] + b2, v3 = acc[r][3] + b3;
            *(float4*)&h2p[i * H2P_STR + cb] = make_float4(v0, v1, v2, v3);
            float ssum = v0*wa0 + v1*wa1v + v2*wa2v + v3*wa3;
            float tsum = v0*wb0 + v1*wb1v + v2*wb2v + v3*wb3;
            ssum += __shfl_xor_sync(0xffffffffu, ssum, 1);
            ssum += __shfl_xor_sync(0xffffffffu, ssum, 2);
            tsum += __shfl_xor_sync(0xffffffffu, tsum, 1);
            tsum += __shfl_xor_sync(0xffffffffu, tsum, 2);
            if (cg == 0) {
                atomicAdd(&s2[i], ssum);
                atomicAdd(&t2[i], tsum);
            }
        }
    }
    __syncthreads();

    float ba = ba2[0];
    const float* adjg = g_adj + (size_t)b * K1P * K1P;
    for (int idx = t; idx < K1P * K1P; idx += 256) {
        int i = idx / K1P, j = idx - i * K1P;
        float e = s2[i] + t2[j] + ba;
        e = e > 0.f ? e : 0.f;
        atts[i * ATT_STR + j] = expf(e) * adjg[idx];
    }
    __syncthreads();
    if (t < K1P) {
        float s = 0.f;
        for (int j = 0; j < K1P; j++) s += atts[t * ATT_STR + j];
        invr[t] = 1.f / s;
    }
    __syncthreads();

    float acc2[7][4];
    #pragma unroll
    for (int r = 0; r < 7; r++) { acc2[r][0]=0.f; acc2[r][1]=0.f; acc2[r][2]=0.f; acc2[r][3]=0.f; }
    #pragma unroll 2
    for (int j4 = 0; j4 < 14; j4++) {
        float4 b0 = *(const float4*)&h2p[(j4 * 4 + 0) * H2P_STR + cb];
        float4 b1 = *(const float4*)&h2p[(j4 * 4 + 1) * H2P_STR + cb];
        float4 b2 = *(const float4*)&h2p[(j4 * 4 + 2) * H2P_STR + cb];
        float4 b3 = *(const float4*)&h2p[(j4 * 4 + 3) * H2P_STR + cb];
        #pragma unroll
        for (int r = 0; r < 7; r++) {
            float4 a = *(const float4*)&atts[(row0 + r) * ATT_STR + j4 * 4];
            acc2[r][0] = fmaf(a.x, b0.x, acc2[r][0]);
            acc2[r][1] = fmaf(a.x, b0.y, acc2[r][1]);
            acc2[r][2] = fmaf(a.x, b0.z, acc2[r][2]);
            acc2[r][3] = fmaf(a.x, b0.w, acc2[r][3]);
            acc2[r][0] = fmaf(a.y, b1.x, acc2[r][0]);
            acc2[r][1] = fmaf(a.y, b1.y, acc2[r][1]);
            acc2[r][2] = fmaf(a.y, b1.z, acc2[r][2]);
            acc2[r][3] = fmaf(a.y, b1.w, acc2[r][3]);
            acc2[r][0] = fmaf(a.z, b2.x, acc2[r][0]);
            acc2[r][1] = fmaf(a.z, b2.y, acc2[r][1]);
            acc2[r][2] = fmaf(a.z, b2.z, acc2[r][2]);
            acc2[r][3] = fmaf(a.z, b2.w, acc2[r][3]);
            acc2[r][0] = fmaf(a.w, b3.x, acc2[r][0]);
            acc2[r][1] = fmaf(a.w, b3.y, acc2[r][1]);
            acc2[r][2] = fmaf(a.w, b3.z, acc2[r][2]);
            acc2[r][3] = fmaf(a.w, b3.w, acc2[r][3]);
        }
    }
    __syncthreads();
    {
        const float* wpp = Wpool2 + cb;
        float w0 = wpp[0], w1 = wpp[1], w2 = wpp[2], w3 = wpp[3];
        #pragma unroll
        for (int r = 0; r < 7; r++) {
            int i = row0 + r;
            float ir = invr[i];
            float4 hself = *(const float4*)&h2p[i * H2P_STR + cb];
            float4 v;
            v.x = fmaxf(fmaf(acc2[r][0], ir, hself.x), 0.f);
            v.y = fmaxf(fmaf(acc2[r][1], ir, hself.y), 0.f);
            v.z = fmaxf(fmaf(acc2[r][2], ir, hself.z), 0.f);
            v.w = fmaxf(fmaf(acc2[r][3], ir, hself.w), 0.f);
            *(float4*)&h2p[i * H2P_STR + cb] = v;
            float sp = v.x*w0 + v.y*w1 + v.z*w2 + v.w*w3;
            sp += __shfl_xor_sync(0xffffffffu, sp, 1);
            sp += __shfl_xor_sync(0xffffffffu, sp, 2);
            if (cg == 0) atomicAdd(&sc2[i], sp);
        }
    }
    __syncthreads();

    if (t < 64) {
        if (t < K1P) {
            skey[t] = 1.f / (1.f + expf(-(sc2[t] + bpool2[0])));
            sidx[t] = t;
        } else { skey[t] = -1.f; sidx[t] = t; }
    }
    __syncthreads();
    for (int k = 2; k <= 64; k <<= 1) {
        for (int j = k >> 1; j > 0; j >>= 1) {
            if (t < 64) {
                int lp = t ^ j;
                if (lp > t) {
                    float a = skey[t], c = skey[lp];
                    int ia = sidx[t], ib = sidx[lp];
                    bool before = (a > c) || (a == c && ia < ib);
                    if (((t & k) == 0) ? !before : before) {
                        skey[t] = c; skey[lp] = a;
                        sidx[t] = ib; sidx[lp] = ia;
                    }
                }
            }
            __syncthreads();
        }
    }

    if (t < L2D) {
        float s = 0.f;
        #pragma unroll 4
        for (int m = 0; m < K2P; m++)
            s += h2p[sidx[m] * H2P_STR + t] * skey[m];
        mvec[t] = s * (1.f / (float)K2P);
    }
    __syncthreads();
    if (t < L3D) {
        float s = bfc1[t];
        #pragma unroll 8
        for (int d = 0; d < L2D; d++) s = fmaf(mvec[d], Wfc1[t * L2D + d], s);
        y1[t] = fmaxf(s, 0.f);
    }
    __syncthreads();
    if (t == 0) {
        float s = bfc2[0];
        for (int o = 0; o < L3D; o++) s = fmaf(y1[o], Wfc2[o], s);
        out[b] = s;
    }
}

// ---------------- launch ----------------
extern "C" void kernel_launch(void* const* d_in, const int* in_sizes, int n_in,
                              void* d_out, int out_size) {
    const float* x      = (const float*)d_in[0];
    const float* Wp1    = (const float*)d_in[1];
    const float* bp1    = (const float*)d_in[2];
    const float* wa1    = (const float*)d_in[3];
    const float* wb1    = (const float*)d_in[4];
    const float* ba1    = (const float*)d_in[5];
    const float* Wpool1 = (const float*)d_in[6];
    const float* bpool1 = (const float*)d_in[7];
    const float* Wp2    = (const float*)d_in[8];
    const float* bp2    = (const float*)d_in[9];
    const float* wa2    = (const float*)d_in[10];
    const float* wb2    = (const float*)d_in[11];
    const float* ba2    = (const float*)d_in[12];
    const float* Wpool2 = (const float*)d_in[13];
    const float* bpool2 = (const float*)d_in[14];
    const float* Wfc1   = (const float*)d_in[15];
    const float* bfc1   = (const float*)d_in[16];
    const float* Wfc2   = (const float*)d_in[17];
    const float* bfc2   = (const float*)d_in[18];
    float* out = (float*)d_out;

    size_t smem1 = (size_t)V_TOT * sizeof(float);
    size_t smem2 = (size_t)G2_FLOATS * sizeof(float);
    cudaFuncSetAttribute(k_gat1, cudaFuncAttributeMaxDynamicSharedMemorySize, (int)smem1);
    cudaFuncSetAttribute(k_gat2, cudaFuncAttributeMaxDynamicSharedMemorySize, (int)smem2);

    k_preA<<<32, 256>>>(Wp1, bp1, Wp2);
    k_preB<<<1, 256>>>(wa1, wb1, ba1);
    k_tail<<<1, 32>>>();
    k_gat1<<<BATCH, 256, smem1>>>(x, Wpool1, bpool1);
    k_gat2<<<BATCH, 256, smem2>>>(bp2, wa2, wb2, ba2, Wpool2, bpool2,
                                  Wfc1, bfc1, Wfc2, bfc2, out);
}

// round 17
// speedup vs baseline: 1.1564x; 1.1030x over previous
#include <cuda_runtime.h>
#include <math.h>
#include <stdint.h>

#define NODE 112
#define L1D 256
#define L2D 128
#define L3D 64
#define BATCH 2048
#define K1P 56
#define K2P 28

// ---------------- f32x2 packed-FMA helpers (sm_103a FFMA2) ----------------
__device__ __forceinline__ void fma2(uint64_t& d, uint64_t a, uint64_t b) {
    asm("fma.rn.f32x2 %0, %1, %2, %0;" : "+l"(d) : "l"(a), "l"(b));
}
__device__ __forceinline__ uint64_t dup2(float a) {
    uint64_t r; asm("mov.b64 %0, {%1, %1};" : "=l"(r) : "f"(a)); return r;
}
__device__ __forceinline__ float2 unpk(uint64_t v) {
    float2 r; asm("mov.b64 {%0, %1}, %2;" : "=f"(r.x), "=f"(r.y) : "l"(v)); return r;
}

// ---------------- global scratch ----------------
__device__ float g_H0[NODE * L1D];            // projected identity features [n][o]
__device__ float g_E1[NODE * NODE];
__device__ float g_Wp2T[L1D * L2D];           // Wp2 transposed [d][o]
__device__ float g_h1[(size_t)BATCH * NODE * L1D];
__device__ float g_hp[(size_t)BATCH * K1P * L1D];
__device__ float g_adj[(size_t)BATCH * K1P * K1P];
__device__ float g_dummy;

// ---------------- K-preA ----------------
__global__ void k_preA(const float* __restrict__ Wp1, const float* __restrict__ bp1,
                       const float* __restrict__ Wp2) {
    int t = blockIdx.x * blockDim.x + threadIdx.x;
    int NT = gridDim.x * blockDim.x;
    for (int idx = t; idx < NODE * L1D; idx += NT) {
        int o = idx / NODE, n = idx - o * NODE;
        g_H0[n * L1D + o] = Wp1[idx] + bp1[o];
    }
    for (int idx = t; idx < L1D * L2D; idx += NT) {
        int o = idx >> 8, d = idx & 255;
        g_Wp2T[d * L2D + o] = Wp2[idx];
    }
}

// ---------------- K-preB ----------------
__global__ void k_preB(const float* __restrict__ wa1, const float* __restrict__ wb1,
                       const float* __restrict__ ba1) {
    __shared__ float s1[NODE], t1[NODE];
    int t = threadIdx.x;
    if (t < NODE) {
        float ss = 0.f, tt = 0.f;
        #pragma unroll 4
        for (int o = 0; o < L1D; o++) {
            float h = g_H0[t * L1D + o];
            ss = fmaf(h, wa1[o], ss);
            tt = fmaf(h, wb1[o], tt);
        }
        s1[t] = ss; t1[t] = tt;
    }
    __syncthreads();
    float ba = ba1[0];
    for (int idx = t; idx < NODE * NODE; idx += blockDim.x) {
        int i = idx / NODE, j = idx - i * NODE;
        float e = s1[i] + t1[j] + ba;
        e = e > 0.f ? e : 0.f;
        g_E1[idx] = expf(e);
    }
}

__global__ void k_tail() { if (threadIdx.x == 0) g_dummy = 1.f; }

// ---------------- K2: GAT1 + pool1 (occ 3, row-halves, k-split, fma2) -----
#define V_WS_STR 116
#define V_WS    0
#define V_H0T   (56 * V_WS_STR)                // 6496
#define V_INVR  (V_H0T + 56 * 128)             // 13664
#define V_SCR   (V_INVR + 64)
#define V_SKEY  (V_SCR + 128)
#define V_SIDX  (V_SKEY + 128)
#define V_TOT   (V_SIDX + 128)                 // 14112 floats = 56448 B

__global__ void __launch_bounds__(256, 3)
k_gat1(const float* __restrict__ x, const float* __restrict__ Wpool1,
       const float* __restrict__ bpool1) {
    extern __shared__ float sm[];
    float* Ws   = sm + V_WS;
    float* H0t  = sm + V_H0T;                  // [56 k-rows][128 cols]
    float* invr = sm + V_INVR;
    float* scr  = sm + V_SCR;
    float* skey = sm + V_SKEY;
    int*   sidx = (int*)(sm + V_SIDX);
    float* adjb = sm + V_H0T;                  // overlay

    int b = blockIdx.x;
    int t = threadIdx.x;
    const float* xb = x + (size_t)b * NODE * NODE;
    int l = t & 31, w = t >> 5;
    int rg = l >> 2, cg = l & 3;
    int row0 = rg * 7;                         // rows within half (0..55)
    int cb = w * 16 + cg * 4;                  // cols within 128-col tile
    float* h1b = g_h1 + (size_t)b * NODE * L1D;

    if (t < NODE) scr[t] = 0.f;

    for (int half = 0; half < 2; half++) {
        int rbase = half * 56;
        __syncthreads();
        for (int idx = t; idx < 56 * NODE; idx += 256) {
            int i2 = idx / NODE, j = idx - i2 * NODE;
            int gi = (rbase + i2) * NODE + j;
            Ws[i2 * V_WS_STR + j] = g_E1[gi] * xb[gi];
        }
        __syncthreads();
        {
            int i2 = w * 7;
            #pragma unroll
            for (int rr = 0; rr < 7; rr++, i2++) {
                const float* wr = &Ws[i2 * V_WS_STR];
                float s = wr[l] + wr[32 + l] + wr[64 + l];
                if (l < 16) s += wr[96 + l];
                s += __shfl_xor_sync(0xffffffffu, s, 16);
                s += __shfl_xor_sync(0xffffffffu, s, 8);
                s += __shfl_xor_sync(0xffffffffu, s, 4);
                s += __shfl_xor_sync(0xffffffffu, s, 2);
                s += __shfl_xor_sync(0xffffffffu, s, 1);
                if (l == 0) invr[i2] = 1.f / s;
            }
        }
        for (int ct = 0; ct < 2; ct++) {       // 128-col tiles
            uint64_t acc[7][2];
            #pragma unroll
            for (int r = 0; r < 7; r++) { acc[r][0] = 0ull; acc[r][1] = 0ull; }
            #pragma unroll
            for (int s5 = 0; s5 < 2; s5++) {
                int kh = (s5 == 0) ? (half ^ 1) : half;   // own-rows tile last
                __syncthreads();
                for (int idx = t; idx < 56 * 128; idx += 256) {
                    int jr = idx >> 7, c = idx & 127;
                    H0t[idx] = g_H0[(kh * 56 + jr) * L1D + ct * 128 + c];
                }
                __syncthreads();
                int kb = kh * 56;
                #pragma unroll 2
                for (int j4 = 0; j4 < 14; j4++) {
                    ulonglong2 b0 = *(const ulonglong2*)&H0t[(j4 * 4 + 0) * 128 + cb];
                    ulonglong2 b1 = *(const ulonglong2*)&H0t[(j4 * 4 + 1) * 128 + cb];
                    ulonglong2 b2 = *(const ulonglong2*)&H0t[(j4 * 4 + 2) * 128 + cb];
                    ulonglong2 b3 = *(const ulonglong2*)&H0t[(j4 * 4 + 3) * 128 + cb];
                    #pragma unroll
                    for (int r = 0; r < 7; r++) {
                        float4 a = *(const float4*)&Ws[(row0 + r) * V_WS_STR + kb + j4 * 4];
                        uint64_t ax = dup2(a.x), ay = dup2(a.y);
                        uint64_t az = dup2(a.z), aw = dup2(a.w);
                        fma2(acc[r][0], ax, b0.x); fma2(acc[r][1], ax, b0.y);
                        fma2(acc[r][0], ay, b1.x); fma2(acc[r][1], ay, b1.y);
                        fma2(acc[r][0], az, b2.x); fma2(acc[r][1], az, b2.y);
                        fma2(acc[r][0], aw, b3.x); fma2(acc[r][1], aw, b3.y);
                    }
                }
            }
            // epilogue: H0t holds this half's own rows (k-rows == out rows)
            float wc0 = Wpool1[ct * 128 + cb];
            float wc1 = Wpool1[ct * 128 + cb + 1];
            float wc2 = Wpool1[ct * 128 + cb + 2];
            float wc3 = Wpool1[ct * 128 + cb + 3];
            #pragma unroll
            for (int r = 0; r < 7; r++) {
                int i2 = row0 + r;
                int ig = rbase + i2;
                float ir = invr[i2];
                float4 h0 = *(const float4*)&H0t[i2 * 128 + cb];
                float2 c01 = unpk(acc[r][0]);
                float2 c23 = unpk(acc[r][1]);
                float4 v;
                v.x = fmaxf(fmaf(c01.x, ir, h0.x), 0.f);
                v.y = fmaxf(fmaf(c01.y, ir, h0.y), 0.f);
                v.z = fmaxf(fmaf(c23.x, ir, h0.z), 0.f);
                v.w = fmaxf(fmaf(c23.y, ir, h0.w), 0.f);
                *(float4*)&h1b[ig * L1D + ct * 128 + cb] = v;
                float sp = v.x*wc0 + v.y*wc1 + v.z*wc2 + v.w*wc3;
                sp += __shfl_xor_sync(0xffffffffu, sp, 1);
                sp += __shfl_xor_sync(0xffffffffu, sp, 2);
                if (cg == 0) atomicAdd(&scr[ig], sp);
            }
        }
    }
    __syncthreads();

    // sigmoid + bitonic top-56 (pad 128)
    if (t < 128) {
        if (t < NODE) {
            skey[t] = 1.f / (1.f + expf(-(scr[t] + bpool1[0])));
            sidx[t] = t;
        } else { skey[t] = -1.f; sidx[t] = t; }
    }
    __syncthreads();
    for (int k = 2; k <= 128; k <<= 1) {
        for (int j = k >> 1; j > 0; j >>= 1) {
            if (t < 128) {
                int lp = t ^ j;
                if (lp > t) {
                    float a = skey[t], c = skey[lp];
                    int ia = sidx[t], ib = sidx[lp];
                    bool before = (a > c) || (a == c && ia < ib);
                    if (((t & k) == 0) ? !before : before) {
                        skey[t] = c; skey[lp] = a;
                        sidx[t] = ib; sidx[lp] = ia;
                    }
                }
            }
            __syncthreads();
        }
    }

    float* hpb = g_hp + (size_t)b * K1P * L1D;
    for (int idx = t; idx < K1P * L1D; idx += 256) {
        int m = idx >> 8, c = idx & 255;
        hpb[idx] = h1b[sidx[m] * L1D + c] * skey[m];
    }
    for (int idx = t; idx < K1P * K1P; idx += 256) {
        int i = idx / K1P, j = idx - i * K1P;
        adjb[i * 57 + j] = xb[sidx[i] * NODE + sidx[j]];
    }
    __syncthreads();
    if (t < K1P) {
        float s = 0.f;
        for (int j = 0; j < K1P; j++) s += adjb[t * 57 + j];
        invr[t] = 1.f / s;
    }
    __syncthreads();
    float* adjo = g_adj + (size_t)b * K1P * K1P;
    for (int idx = t; idx < K1P * K1P; idx += 256) {
        int i = idx / K1P, j = idx - i * K1P;
        adjo[idx] = adjb[i * 57 + j] * invr[i];
    }
}

// ---------------- K3: GAT2 + pool2 + mean + FC head (occ 3, fma2) ---------
#define HST_STR  36
#define ATT_STR  60
#define H2P_STR  132
#define G2_OVL   0
#define G2_W2P   (56 * HST_STR)               // 2016
#define G2_H2P   6112
#define G2_S2    (G2_H2P + K1P * H2P_STR)     // 13504
#define G2_T2    (G2_S2 + 64)
#define G2_SC2   (G2_T2 + 64)
#define G2_INVR  (G2_SC2 + 64)
#define G2_SKEY  (G2_INVR + 64)
#define G2_SIDX  (G2_SKEY + 64)
#define G2_MVEC  (G2_SIDX + 64)
#define G2_Y1    (G2_MVEC + 128)
#define G2_FLOATS (G2_Y1 + 64)

__global__ void __launch_bounds__(256, 3)
k_gat2(const float* __restrict__ bp2, const float* __restrict__ wa2,
       const float* __restrict__ wb2, const float* __restrict__ ba2,
       const float* __restrict__ Wpool2, const float* __restrict__ bpool2,
       const float* __restrict__ Wfc1, const float* __restrict__ bfc1,
       const float* __restrict__ Wfc2, const float* __restrict__ bfc2,
       float* __restrict__ out) {
    extern __shared__ float sm[];
    float* Hst  = sm + G2_OVL;
    float* W2p  = sm + G2_W2P;
    float* atts = sm + G2_OVL;
    float* h2p  = sm + G2_H2P;
    float* s2   = sm + G2_S2;
    float* t2   = sm + G2_T2;
    float* sc2  = sm + G2_SC2;
    float* invr = sm + G2_INVR;
    float* skey = sm + G2_SKEY;
    int*   sidx = (int*)(sm + G2_SIDX);
    float* mvec = sm + G2_MVEC;
    float* y1   = sm + G2_Y1;

    int b = blockIdx.x;
    int t = threadIdx.x;
    const float* hpb = g_hp + (size_t)b * K1P * L1D;

    if (t < K1P) { s2[t] = 0.f; t2[t] = 0.f; sc2[t] = 0.f; }

    int l = t & 31, w = t >> 5;
    int rg = l >> 2, cg = l & 3;
    int row0 = rg * 7;
    int cb = w * 16 + cg * 4;

    // GEMM1: h2 = Hs @ Wp2^T + bp2 (56x256 @ 256x128), K tiled by 32
    uint64_t acc[7][2];
    #pragma unroll
    for (int r = 0; r < 7; r++) { acc[r][0] = 0ull; acc[r][1] = 0ull; }
    for (int dt = 0; dt < 8; dt++) {
        for (int idx = t; idx < 56 * 32; idx += 256) {
            int i = idx >> 5, dd = idx & 31;
            Hst[i * HST_STR + dd] = hpb[i * L1D + dt * 32 + dd];
        }
        for (int idx = t; idx < 32 * 128; idx += 256)
            W2p[idx] = g_Wp2T[dt * 4096 + idx];
        __syncthreads();
        #pragma unroll
        for (int d4 = 0; d4 < 8; d4++) {
            ulonglong2 b0 = *(const ulonglong2*)&W2p[(d4 * 4 + 0) * 128 + cb];
            ulonglong2 b1 = *(const ulonglong2*)&W2p[(d4 * 4 + 1) * 128 + cb];
            ulonglong2 b2 = *(const ulonglong2*)&W2p[(d4 * 4 + 2) * 128 + cb];
            ulonglong2 b3 = *(const ulonglong2*)&W2p[(d4 * 4 + 3) * 128 + cb];
            #pragma unroll
            for (int r = 0; r < 7; r++) {
                float4 a = *(const float4*)&Hst[(row0 + r) * HST_STR + d4 * 4];
                uint64_t ax = dup2(a.x), ay = dup2(a.y);
                uint64_t az = dup2(a.z), aw = dup2(a.w);
                fma2(acc[r][0], ax, b0.x); fma2(acc[r][1], ax, b0.y);
                fma2(acc[r][0], ay, b1.x); fma2(acc[r][1], ay, b1.y);
                fma2(acc[r][0], az, b2.x); fma2(acc[r][1], az, b2.y);
                fma2(acc[r][0], aw, b3.x); fma2(acc[r][1], aw, b3.y);
            }
        }
        __syncthreads();
    }
    {
        const float* bpp = bp2 + cb;
        float b0 = bpp[0], b1 = bpp[1], b2 = bpp[2], b3 = bpp[3];
        const float* wap = wa2 + cb;
        const float* wbp = wb2 + cb;
        float wa0=wap[0], wa1v=wap[1], wa2v=wap[2], wa3=wap[3];
        float wb0=wbp[0], wb1v=wbp[1], wb2v=wbp[2], wb3=wbp[3];
        #pragma unroll
        for (int r = 0; r < 7; r++) {
            int i = row0 + r;
            float2 c01 = unpk(acc[r][0]);
            float2 c23 = unpk(acc[r][1]);
            float v0 = c01.x + b0, v1 = c01.y + b1;
            float v2 = c23.x + b2, v3 = c23.y + b3;
            *(float4*)&h2p[i * H2P_STR + cb] = make_float4(v0, v1, v2, v3);
            float ssum = v0*wa0 + v1*wa1v + v2*wa2v + v3*wa3;
            float tsum = v0*wb0 + v1*wb1v + v2*wb2v + v3*wb3;
            ssum += __shfl_xor_sync(0xffffffffu, ssum, 1);
            ssum += __shfl_xor_sync(0xffffffffu, ssum, 2);
            tsum += __shfl_xor_sync(0xffffffffu, tsum, 1);
            tsum += __shfl_xor_sync(0xffffffffu, tsum, 2);
            if (cg == 0) {
                atomicAdd(&s2[i], ssum);
                atomicAdd(&t2[i], tsum);
            }
        }
    }
    __syncthreads();

    // attention weights (atts overlays Hst/W2p)
    float ba = ba2[0];
    const float* adjg = g_adj + (size_t)b * K1P * K1P;
    for (int idx = t; idx < K1P * K1P; idx += 256) {
        int i = idx / K1P, j = idx - i * K1P;
        float e = s2[i] + t2[j] + ba;
        e = e > 0.f ? e : 0.f;
        atts[i * ATT_STR + j] = expf(e) * adjg[idx];
    }
    __syncthreads();
    if (t < K1P) {
        float s = 0.f;
        for (int j = 0; j < K1P; j++) s += atts[t * ATT_STR + j];
        invr[t] = 1.f / s;
    }
    __syncthreads();

    // GEMM2: out2 = att_norm @ h2 + h2, relu (in-place into h2p)
    uint64_t acc2[7][2];
    #pragma unroll
    for (int r = 0; r < 7; r++) { acc2[r][0] = 0ull; acc2[r][1] = 0ull; }
    #pragma unroll 2
    for (int j4 = 0; j4 < 14; j4++) {
        ulonglong2 b0 = *(const ulonglong2*)&h2p[(j4 * 4 + 0) * H2P_STR + cb];
        ulonglong2 b1 = *(const ulonglong2*)&h2p[(j4 * 4 + 1) * H2P_STR + cb];
        ulonglong2 b2 = *(const ulonglong2*)&h2p[(j4 * 4 + 2) * H2P_STR + cb];
        ulonglong2 b3 = *(const ulonglong2*)&h2p[(j4 * 4 + 3) * H2P_STR + cb];
        #pragma unroll
        for (int r = 0; r < 7; r++) {
            float4 a = *(const float4*)&atts[(row0 + r) * ATT_STR + j4 * 4];
            uint64_t ax = dup2(a.x), ay = dup2(a.y);
            uint64_t az = dup2(a.z), aw = dup2(a.w);
            fma2(acc2[r][0], ax, b0.x); fma2(acc2[r][1], ax, b0.y);
            fma2(acc2[r][0], ay, b1.x); fma2(acc2[r][1], ay, b1.y);
            fma2(acc2[r][0], az, b2.x); fma2(acc2[r][1], az, b2.y);
            fma2(acc2[r][0], aw, b3.x); fma2(acc2[r][1], aw, b3.y);
        }
    }
    __syncthreads();
    {
        const float* wpp = Wpool2 + cb;
        float w0 = wpp[0], w1 = wpp[1], w2 = wpp[2], w3 = wpp[3];
        #pragma unroll
        for (int r = 0; r < 7; r++) {
            int i = row0 + r;
            float ir = invr[i];
            float4 hself = *(const float4*)&h2p[i * H2P_STR + cb];
            float2 c01 = unpk(acc2[r][0]);
            float2 c23 = unpk(acc2[r][1]);
            float4 v;
            v.x = fmaxf(fmaf(c01.x, ir, hself.x), 0.f);
            v.y = fmaxf(fmaf(c01.y, ir, hself.y), 0.f);
            v.z = fmaxf(fmaf(c23.x, ir, hself.z), 0.f);
            v.w = fmaxf(fmaf(c23.y, ir, hself.w), 0.f);
            *(float4*)&h2p[i * H2P_STR + cb] = v;
            float sp = v.x*w0 + v.y*w1 + v.z*w2 + v.w*w3;
            sp += __shfl_xor_sync(0xffffffffu, sp, 1);
            sp += __shfl_xor_sync(0xffffffffu, sp, 2);
            if (cg == 0) atomicAdd(&sc2[i], sp);
        }
    }
    __syncthreads();

    // top-28 of 56 (pad 64)
    if (t < 64) {
        if (t < K1P) {
            skey[t] = 1.f / (1.f + expf(-(sc2[t] + bpool2[0])));
            sidx[t] = t;
        } else { skey[t] = -1.f; sidx[t] = t; }
    }
    __syncthreads();
    for (int k = 2; k <= 64; k <<= 1) {
        for (int j = k >> 1; j > 0; j >>= 1) {
            if (t < 64) {
                int lp = t ^ j;
                if (lp > t) {
                    float a = skey[t], c = skey[lp];
                    int ia = sidx[t], ib = sidx[lp];
                    bool before = (a > c) || (a == c && ia < ib);
                    if (((t & k) == 0) ? !before : before) {
                        skey[t] = c; skey[lp] = a;
                        sidx[t] = ib; sidx[lp] = ia;
                    }
                }
            }
            __syncthreads();
        }
    }

    if (t < L2D) {
        float s = 0.f;
        #pragma unroll 4
        for (int m = 0; m < K2P; m++)
            s += h2p[sidx[m] * H2P_STR + t] * skey[m];
        mvec[t] = s * (1.f / (float)K2P);
    }
    __syncthreads();
    if (t < L3D) {
        float s = bfc1[t];
        #pragma unroll 8
        for (int d = 0; d < L2D; d++) s = fmaf(mvec[d], Wfc1[t * L2D + d], s);
        y1[t] = fmaxf(s, 0.f);
    }
    __syncthreads();
    if (t == 0) {
        float s = bfc2[0];
        for (int o = 0; o < L3D; o++) s = fmaf(y1[o], Wfc2[o], s);
        out[b] = s;
    }
}

// ---------------- launch ----------------
extern "C" void kernel_launch(void* const* d_in, const int* in_sizes, int n_in,
                              void* d_out, int out_size) {
    const float* x      = (const float*)d_in[0];
    const float* Wp1    = (const float*)d_in[1];
    const float* bp1    = (const float*)d_in[2];
    const float* wa1    = (const float*)d_in[3];
    const float* wb1    = (const float*)d_in[4];
    const float* ba1    = (const float*)d_in[5];
    const float* Wpool1 = (const float*)d_in[6];
    const float* bpool1 = (const float*)d_in[7];
    const float* Wp2    = (const float*)d_in[8];
    const float* bp2    = (const float*)d_in[9];
    const float* wa2    = (const float*)d_in[10];
    const float* wb2    = (const float*)d_in[11];
    const float* ba2    = (const float*)d_in[12];
    const float* Wpool2 = (const float*)d_in[13];
    const float* bpool2 = (const float*)d_in[14];
    const float* Wfc1   = (const float*)d_in[15];
    const float* bfc1   = (const float*)d_in[16];
    const float* Wfc2   = (const float*)d_in[17];
    const float* bfc2   = (const float*)d_in[18];
    float* out = (float*)d_out;

    size_t smem1 = (size_t)V_TOT * sizeof(float);
    size_t smem2 = (size_t)G2_FLOATS * sizeof(float);
    cudaFuncSetAttribute(k_gat1, cudaFuncAttributeMaxDynamicSharedMemorySize, (int)smem1);
    cudaFuncSetAttribute(k_gat2, cudaFuncAttributeMaxDynamicSharedMemorySize, (int)smem2);

    k_preA<<<32, 256>>>(Wp1, bp1, Wp2);
    k_preB<<<1, 256>>>(wa1, wb1, ba1);
    k_tail<<<1, 32>>>();
    k_gat1<<<BATCH, 256, smem1>>>(x, Wpool1, bpool1);
    k_gat2<<<BATCH, 256, smem2>>>(bp2, wa2, wb2, ba2, Wpool2, bpool2,
                                  Wfc1, bfc1, Wfc2, bfc2, out);
}